// round 16
// baseline (speedup 1.0000x reference)
#include <cuda_runtime.h>
#include <cuda_bf16.h>

#define HH  2048
#define DD  1024
#define TT  4096
#define G3H 6144   // 3*HH

#define NB      148            // persistent blocks
#define GB      74             // blocks per barrier group (one group per GRU)
#define NW      28             // warps per block; 74*28 = 2072 >= 2048 outputs per GRU
#define THREADS (NW * 32)

// ---------------- device scratch (allocation-free rule: __device__ globals) ---
__device__ float g_xp[2][TT][G3H];                 // ~201 MB precomputed input projections
__device__ __nv_bfloat16 g_xb[2][TT][DD];          // bf16 x
__device__ __nv_bfloat16 g_wb[2][G3H][DD];         // bf16 W_ih
__device__ char  g_wq[2][G3H][HH];                 // int8 quantized W_hh
__device__ float g_wdq[2][G3H];                    // per-row dequant factor
__device__ __align__(16) char g_hq[2][2][HH];      // [buffer][gru][H] int8 h (scale 1/127)
__device__ float g_h32[2 * HH];                    // final fp32 h for the head
__device__ unsigned int g_bar2[2][64];             // per-group counters, 256B apart
__device__ float g_fc1[256];

// ---------------- prep: reset barriers, zero h0 ------------------------------
__global__ void prep_kernel() {
    if (threadIdx.x < 128) ((unsigned int*)g_bar2)[threadIdx.x] = 0u;
    for (int j = threadIdx.x; j < 1024; j += blockDim.x)
        ((unsigned int*)g_hq[0])[j] = 0u;
}

// ---------------- convert x, W_ih to bf16 ------------------------------------
__global__ void conv_bf16(const float* __restrict__ x1, const float* __restrict__ x2,
                          const float* __restrict__ W1, const float* __restrict__ W2) {
    const long long idx    = (long long)blockIdx.x * blockDim.x + threadIdx.x;
    const long long stride = (long long)gridDim.x * blockDim.x;
    const long long NX = (long long)TT * DD;
    const long long NW_ = (long long)G3H * DD;
    for (long long i = idx; i < NX; i += stride) {
        ((__nv_bfloat16*)g_xb[0])[i] = __float2bfloat16(x1[i]);
        ((__nv_bfloat16*)g_xb[1])[i] = __float2bfloat16(x2[i]);
    }
    for (long long i = idx; i < NW_; i += stride) {
        ((__nv_bfloat16*)g_wb[0])[i] = __float2bfloat16(W1[i]);
        ((__nv_bfloat16*)g_wb[1])[i] = __float2bfloat16(W2[i]);
    }
}

// ---------------- quantize W_hh rows to int8 ---------------------------------
__global__ void quant_kernel(const float* __restrict__ W1, const float* __restrict__ W2) {
    const int bi  = blockIdx.x;
    const int gru = bi / G3H;
    const int row = bi % G3H;
    const float* __restrict__ src = (gru ? W2 : W1) + (size_t)row * HH;
    __shared__ float red[256];
    const int tid = threadIdx.x;

    float m = 0.f;
    for (int j = tid; j < HH; j += 256) m = fmaxf(m, fabsf(src[j]));
    red[tid] = m; __syncthreads();
    for (int o = 128; o; o >>= 1) { if (tid < o) red[tid] = fmaxf(red[tid], red[tid + o]); __syncthreads(); }
    m = red[0];
    const float inv = (m > 0.f) ? 127.f / m : 0.f;
    if (tid == 0) g_wdq[gru][row] = m / (127.f * 127.f);

    unsigned int* dst = (unsigned int*)&g_wq[gru][row][0];
#pragma unroll
    for (int v = 0; v < 2; v++) {
        const int e = tid * 8 + v * 4;
        unsigned int p = 0;
#pragma unroll
        for (int b = 0; b < 4; b++) {
            int q = __float2int_rn(src[e + b] * inv);
            q = max(-127, min(127, q));
            p |= ((unsigned int)(q & 0xff)) << (b * 8);
        }
        dst[e / 4] = p;
    }
}

// ---------------- xp GEMM via bf16 mma.sync + cp.async double buffer ---------
__device__ __forceinline__ void ldsm4(unsigned int* r, const void* p) {
    unsigned int sa = (unsigned int)__cvta_generic_to_shared(p);
    asm volatile("ldmatrix.sync.aligned.m8n8.x4.shared.b16 {%0,%1,%2,%3}, [%4];"
                 : "=r"(r[0]), "=r"(r[1]), "=r"(r[2]), "=r"(r[3]) : "r"(sa));
}
__device__ __forceinline__ void mma16816(float* c, const unsigned int* a,
                                         unsigned int b0, unsigned int b1) {
    asm volatile("mma.sync.aligned.m16n8k16.row.col.f32.bf16.bf16.f32 "
                 "{%0,%1,%2,%3}, {%4,%5,%6,%7}, {%8,%9}, {%0,%1,%2,%3};"
                 : "+f"(c[0]), "+f"(c[1]), "+f"(c[2]), "+f"(c[3])
                 : "r"(a[0]), "r"(a[1]), "r"(a[2]), "r"(a[3]), "r"(b0), "r"(b1));
}
__device__ __forceinline__ void cpa16(void* smem, const void* gmem) {
    unsigned int sa = (unsigned int)__cvta_generic_to_shared(smem);
    asm volatile("cp.async.cg.shared.global [%0], [%1], 16;" :: "r"(sa), "l"(gmem));
}

__global__ __launch_bounds__(256, 2)
void xp_gemm_mma(const float* __restrict__ bih1, const float* __restrict__ bih2) {
    __shared__ __nv_bfloat16 As[2][128][40];
    __shared__ __nv_bfloat16 Bs[2][128][40];

    const int gru = blockIdx.z;
    const int bm  = blockIdx.y * 128;
    const int bn  = blockIdx.x * 128;
    const __nv_bfloat16* __restrict__ Ag = &g_xb[gru][0][0];
    const __nv_bfloat16* __restrict__ Bg = &g_wb[gru][0][0];
    const float* __restrict__ bias = gru ? bih2 : bih1;

    const int tid  = threadIdx.x;
    const int warp = tid >> 5;
    const int lane = tid & 31;
    const int wm   = warp & 3;
    const int wn   = warp >> 2;

    float acc[2][8][4];
#pragma unroll
    for (int i = 0; i < 2; i++)
#pragma unroll
        for (int j = 0; j < 8; j++)
#pragma unroll
            for (int k = 0; k < 4; k++) acc[i][j][k] = 0.f;

    auto load_slab = [&](int buf, int k0) {
#pragma unroll
        for (int v = 0; v < 2; v++) {
            const int e  = tid + v * 256;
            const int r  = e >> 2;
            const int cc = (e & 3) * 8;
            cpa16(&As[buf][r][cc], Ag + (size_t)(bm + r) * DD + k0 + cc);
            cpa16(&Bs[buf][r][cc], Bg + (size_t)(bn + r) * DD + k0 + cc);
        }
        asm volatile("cp.async.commit_group;");
    };

    load_slab(0, 0);

    int buf = 0;
    for (int k0 = 0; k0 < DD; k0 += 32, buf ^= 1) {
        asm volatile("cp.async.wait_group 0;");
        __syncthreads();
        if (k0 + 32 < DD) load_slab(buf ^ 1, k0 + 32);

#pragma unroll
        for (int kk = 0; kk < 32; kk += 16) {
            unsigned int a[2][4], b[4][4];
            const int arow = (lane & 15);
            const int acol = kk + 8 * (lane >> 4);
#pragma unroll
            for (int mf = 0; mf < 2; mf++)
                ldsm4(a[mf], &As[buf][wm * 32 + mf * 16 + arow][acol]);
#pragma unroll
            for (int nb = 0; nb < 4; nb++)
                ldsm4(b[nb], &Bs[buf][wn * 64 + nb * 16 + arow][acol]);
#pragma unroll
            for (int mf = 0; mf < 2; mf++)
#pragma unroll
                for (int nb = 0; nb < 4; nb++) {
                    mma16816(acc[mf][nb * 2 + 0], a[mf], b[nb][0], b[nb][2]);
                    mma16816(acc[mf][nb * 2 + 1], a[mf], b[nb][1], b[nb][3]);
                }
        }
        __syncthreads();
    }

    float* __restrict__ C = &g_xp[gru][0][0];
#pragma unroll
    for (int nf = 0; nf < 8; nf++) {
        const int gn = bn + wn * 64 + nf * 8 + (lane & 3) * 2;
        const float b0 = __ldg(bias + gn);
        const float b1 = __ldg(bias + gn + 1);
#pragma unroll
        for (int mf = 0; mf < 2; mf++) {
            const int gm = bm + wm * 32 + mf * 16 + (lane >> 2);
            C[(size_t)gm * G3H + gn]           = acc[mf][nf][0] + b0;
            C[(size_t)gm * G3H + gn + 1]       = acc[mf][nf][1] + b1;
            C[(size_t)(gm + 8) * G3H + gn]     = acc[mf][nf][2] + b0;
            C[(size_t)(gm + 8) * G3H + gn + 1] = acc[mf][nf][3] + b1;
        }
    }
}

// ---------------- persistent GRU scan: 2-sync step, reader-side discovery ----
__global__ __launch_bounds__(THREADS, 1)
void gru_scan(const float* __restrict__ bhh1, const float* __restrict__ bhh2) {
    __shared__ uint4 s_r[NW * 128];      // r-gate rows, int8-packed: 56 KB
    __shared__ uint4 s_h[128];           // this GRU's int8 h: 2 KB
    __shared__ char  s_hout[32];         // per-block h bytes (28 used)

    const int tid  = threadIdx.x;
    const int wid  = tid >> 5;
    const int lane = tid & 31;
    const int grp  = (blockIdx.x < GB) ? 0 : 1;          // barrier group == gru
    const int blk  = blockIdx.x - grp * GB;
    const int ol   = blk * NW + wid;                     // local output id
    const bool active = (ol < HH);
    const int i    = active ? ol : 0;
    const int gru  = grp;
    unsigned int* const bar = &g_bar2[grp][0];

    uint4 zr[4], nr[4];
    float fr = 0.f, fz = 0.f, fn = 0.f, br = 0.f, bz = 0.f, bnn = 0.f;
    {
        const uint4* r_row = (const uint4*)&g_wq[gru][i][0];
        const uint4* z_row = (const uint4*)&g_wq[gru][i + HH][0];
        const uint4* n_row = (const uint4*)&g_wq[gru][i + 2 * HH][0];
#pragma unroll
        for (int c = 0; c < 4; c++) {
            s_r[wid * 128 + c * 32 + lane] = r_row[c * 32 + lane];
            zr[c] = z_row[c * 32 + lane];
            nr[c] = n_row[c * 32 + lane];
        }
        fr  = g_wdq[gru][i];
        fz  = g_wdq[gru][i + HH];
        fn  = g_wdq[gru][i + 2 * HH];
        const float* __restrict__ bh = gru ? bhh2 : bhh1;
        br  = bh[i];
        bz  = bh[i + HH];
        bnn = bh[i + 2 * HH];
    }
    float h_own = 0.0f;
    const float* __restrict__ xpg = &g_xp[gru][0][0];

    float xr = 0.f, xz = 0.f, xn = 0.f;
    if (active && lane == 0) {
        xr = __ldg(xpg + i);
        xz = __ldg(xpg + i + HH);
        xn = __ldg(xpg + i + 2 * HH);
    }

    for (int t = 0; t < TT; t++) {
        // ---- stage warps: discover step-t completion, then stage h(t) ----
        if (tid < 128) {
            if (t > 0) {
                const unsigned int target = (unsigned int)GB * (unsigned int)t;
                unsigned int v;
                do {
                    asm volatile("ld.acquire.gpu.global.u32 %0, [%1];"
                                 : "=r"(v) : "l"(bar) : "memory");
                } while (v < target);
            }
            s_h[tid] = __ldcg((const uint4*)g_hq[t & 1][gru] + tid);
        }
        __syncthreads();                                 // s_h ready

        // ---- prefetch xp[t+1] (off the critical chain) ----
        float pxr = 0.f, pxz = 0.f, pxn = 0.f;
        if (active && lane == 0 && t + 1 < TT) {
            const float* __restrict__ xp = xpg + (size_t)(t + 1) * G3H;
            pxr = __ldg(xp + i);
            pxz = __ldg(xp + i + HH);
            pxn = __ldg(xp + i + 2 * HH);
        }

        if (active) {
            int accr = 0, accz = 0, accn = 0;
            const uint4* sr = &s_r[wid * 128];
#pragma unroll
            for (int c = 0; c < 4; c++) {
                uint4 h4 = s_h[c * 32 + lane];
                uint4 r4 = sr[c * 32 + lane];
                accr = __dp4a((int)r4.x, (int)h4.x, accr);
                accr = __dp4a((int)r4.y, (int)h4.y, accr);
                accr = __dp4a((int)r4.z, (int)h4.z, accr);
                accr = __dp4a((int)r4.w, (int)h4.w, accr);
                accz = __dp4a((int)zr[c].x, (int)h4.x, accz);
                accz = __dp4a((int)zr[c].y, (int)h4.y, accz);
                accz = __dp4a((int)zr[c].z, (int)h4.z, accz);
                accz = __dp4a((int)zr[c].w, (int)h4.w, accz);
                accn = __dp4a((int)nr[c].x, (int)h4.x, accn);
                accn = __dp4a((int)nr[c].y, (int)h4.y, accn);
                accn = __dp4a((int)nr[c].z, (int)h4.z, accn);
                accn = __dp4a((int)nr[c].w, (int)h4.w, accn);
            }
            accr = __reduce_add_sync(0xffffffffu, accr);
            accz = __reduce_add_sync(0xffffffffu, accz);
            accn = __reduce_add_sync(0xffffffffu, accn);
            if (lane == 0) {
                const float hr = (float)accr * fr + br;
                const float hz = (float)accz * fz + bz;
                const float hn = (float)accn * fn + bnn;
                const float r = __fdividef(1.f, 1.f + __expf(-(xr + hr)));
                const float z = __fdividef(1.f, 1.f + __expf(-(xz + hz)));
                float n;
                asm("tanh.approx.f32 %0, %1;" : "=f"(n) : "f"(xn + r * hn));
                h_own = (1.f - z) * n + z * h_own;
                int q = __float2int_rn(h_own * 127.f);
                q = max(-127, min(127, q));
                s_hout[wid] = (char)q;
            }
        }
        __syncthreads();                                 // s_hout complete; s_h free

        // ---- warp 0: aggregated h(t+1) writeback + release arrival ----
        if (wid == 0) {
            if (lane < 7) {
                const int byte_off = blk * NW + lane * 4;    // word-aligned (NW=28)
                if (byte_off < HH) {
                    const unsigned int w = ((const unsigned int*)s_hout)[lane];
                    asm volatile("st.global.cg.u32 [%0], %1;"
                                 :: "l"((unsigned int*)(&g_hq[(t + 1) & 1][gru][0] + byte_off)),
                                    "r"(w) : "memory");
                }
            }
            __syncwarp();
            if (lane == 0)
                asm volatile("red.release.gpu.global.add.u32 [%0], %1;"
                             :: "l"(bar), "r"(1u) : "memory");
        }

        xr = pxr; xz = pxz; xn = pxn;
    }

    if (active && lane == 0) g_h32[gru * HH + i] = h_own;
}

// ---------------- head: fc1 (relu) -------------------------------------------
__global__ void head_fc1(const float* __restrict__ w, const float* __restrict__ b) {
    __shared__ float red[256];
    const int row = blockIdx.x, tid = threadIdx.x;
    const float* __restrict__ wr = w + (long long)row * (2 * HH);
    float s = 0.f;
    for (int j = tid; j < 2 * HH; j += 256) s += wr[j] * g_h32[j];
    red[tid] = s; __syncthreads();
    for (int o = 128; o; o >>= 1) { if (tid < o) red[tid] += red[tid + o]; __syncthreads(); }
    if (tid == 0) { const float v = red[0] + b[row]; g_fc1[row] = v > 0.f ? v : 0.f; }
}

// ---------------- head: fc2 + log_softmax ------------------------------------
__global__ void head_fc2(const float* __restrict__ w, const float* __restrict__ b,
                         float* __restrict__ out) {
    __shared__ float logits[3];
    const int tid = threadIdx.x;
    const int wr = tid >> 5, lane = tid & 31;
    float s = 0.f;
    for (int j = lane; j < 256; j += 32) s += w[wr * 256 + j] * g_fc1[j];
#pragma unroll
    for (int off = 16; off; off >>= 1) s += __shfl_down_sync(0xffffffffu, s, off);
    if (lane == 0) logits[wr] = s + b[wr];
    __syncthreads();
    if (tid == 0) {
        const float m = fmaxf(logits[0], fmaxf(logits[1], logits[2]));
        const float l = logf(expf(logits[0] - m) + expf(logits[1] - m) + expf(logits[2] - m));
        out[0] = logits[0] - m - l;
        out[1] = logits[1] - m - l;
        out[2] = logits[2] - m - l;
    }
}

// ---------------- launcher ----------------------------------------------------
extern "C" void kernel_launch(void* const* d_in, const int* in_sizes, int n_in,
                              void* d_out, int out_size) {
    const float* x1    = (const float*)d_in[0];
    const float* x2    = (const float*)d_in[1];
    const float* W_ih1 = (const float*)d_in[2];
    const float* W_hh1 = (const float*)d_in[3];
    const float* b_ih1 = (const float*)d_in[4];
    const float* b_hh1 = (const float*)d_in[5];
    const float* W_ih2 = (const float*)d_in[6];
    const float* W_hh2 = (const float*)d_in[7];
    const float* b_ih2 = (const float*)d_in[8];
    const float* b_hh2 = (const float*)d_in[9];
    const float* fc1_w = (const float*)d_in[10];
    const float* fc1_b = (const float*)d_in[11];
    const float* fc2_w = (const float*)d_in[12];
    const float* fc2_b = (const float*)d_in[13];
    float* out = (float*)d_out;

    prep_kernel<<<1, 256>>>();
    conv_bf16<<<1024, 256>>>(x1, x2, W_ih1, W_ih2);
    quant_kernel<<<2 * G3H, 256>>>(W_hh1, W_hh2);
    xp_gemm_mma<<<dim3(G3H / 128, TT / 128, 2), 256>>>(b_ih1, b_ih2);
    gru_scan<<<NB, THREADS>>>(b_hh1, b_hh2);
    head_fc1<<<256, 256>>>(fc1_w, fc1_b);
    head_fc2<<<1, 96>>>(fc2_w, fc2_b, out);
}

// round 17
// speedup vs baseline: 2.0702x; 2.0702x over previous
#include <cuda_runtime.h>
#include <cuda_bf16.h>

#define HH  2048
#define DD  1024
#define TT  4096
#define G3H 6144   // 3*HH

#define NB      148            // persistent blocks
#define GB      74             // blocks per barrier group (one group per GRU)
#define NW      28             // warps per block; 74*28 = 2072 >= 2048 outputs per GRU
#define THREADS (NW * 32)

// ---------------- device scratch (allocation-free rule: __device__ globals) ---
__device__ float g_xp[2][TT][G3H];                 // ~201 MB precomputed input projections
__device__ __nv_bfloat16 g_xb[2][TT][DD];          // bf16 x
__device__ __nv_bfloat16 g_wb[2][G3H][DD];         // bf16 W_ih
__device__ char  g_wq[2][G3H][HH];                 // int8 quantized W_hh
__device__ float g_wdq[2][G3H];                    // per-row dequant factor
__device__ __align__(16) char g_hq[2][2][HH];      // [buffer][gru][H] int8 h (scale 1/127)
__device__ float g_h32[2 * HH];                    // final fp32 h for the head
__device__ unsigned int g_bar2[2][64];             // per-group counters, 256B apart
__device__ float g_fc1[256];

// ---------------- convert x, W_ih to bf16 (vectorized) ------------------------
__global__ void conv_bf16(const float* __restrict__ x1, const float* __restrict__ x2,
                          const float* __restrict__ W1, const float* __restrict__ W2) {
    const long long idx    = (long long)blockIdx.x * blockDim.x + threadIdx.x;
    const long long stride = (long long)gridDim.x * blockDim.x;
    const long long NX4 = (long long)TT * DD / 4;
    const long long NW4 = (long long)G3H * DD / 4;
    for (long long i = idx; i < NX4; i += stride) {
        float4 a = ((const float4*)x1)[i];
        float4 b = ((const float4*)x2)[i];
        uint2 pa, pb;
        __nv_bfloat162 t;
        t = __floats2bfloat162_rn(a.x, a.y); pa.x = *(unsigned int*)&t;
        t = __floats2bfloat162_rn(a.z, a.w); pa.y = *(unsigned int*)&t;
        t = __floats2bfloat162_rn(b.x, b.y); pb.x = *(unsigned int*)&t;
        t = __floats2bfloat162_rn(b.z, b.w); pb.y = *(unsigned int*)&t;
        ((uint2*)g_xb[0])[i] = pa;
        ((uint2*)g_xb[1])[i] = pb;
    }
    for (long long i = idx; i < NW4; i += stride) {
        float4 a = ((const float4*)W1)[i];
        float4 b = ((const float4*)W2)[i];
        uint2 pa, pb;
        __nv_bfloat162 t;
        t = __floats2bfloat162_rn(a.x, a.y); pa.x = *(unsigned int*)&t;
        t = __floats2bfloat162_rn(a.z, a.w); pa.y = *(unsigned int*)&t;
        t = __floats2bfloat162_rn(b.x, b.y); pb.x = *(unsigned int*)&t;
        t = __floats2bfloat162_rn(b.z, b.w); pb.y = *(unsigned int*)&t;
        ((uint2*)g_wb[0])[i] = pa;
        ((uint2*)g_wb[1])[i] = pb;
    }
}

// ---------------- quantize W_hh rows to int8 (+ fused prep in block 0) -------
__global__ void quant_kernel(const float* __restrict__ W1, const float* __restrict__ W2) {
    const int bi  = blockIdx.x;
    const int gru = bi / G3H;
    const int row = bi % G3H;
    const float* __restrict__ src = (gru ? W2 : W1) + (size_t)row * HH;
    __shared__ float red[256];
    const int tid = threadIdx.x;

    if (bi == 0) {   // fused prep: reset barriers, zero h0 (both GRUs, buffer 0)
        if (tid < 128) ((unsigned int*)g_bar2)[tid] = 0u;
        for (int j = tid; j < 1024; j += 256)
            ((unsigned int*)g_hq[0])[j] = 0u;
    }

    float m = 0.f;
    for (int j = tid; j < HH; j += 256) m = fmaxf(m, fabsf(src[j]));
    red[tid] = m; __syncthreads();
    for (int o = 128; o; o >>= 1) { if (tid < o) red[tid] = fmaxf(red[tid], red[tid + o]); __syncthreads(); }
    m = red[0];
    const float inv = (m > 0.f) ? 127.f / m : 0.f;
    if (tid == 0) g_wdq[gru][row] = m / (127.f * 127.f);

    unsigned int* dst = (unsigned int*)&g_wq[gru][row][0];
#pragma unroll
    for (int v = 0; v < 2; v++) {
        const int e = tid * 8 + v * 4;
        unsigned int p = 0;
#pragma unroll
        for (int b = 0; b < 4; b++) {
            int q = __float2int_rn(src[e + b] * inv);
            q = max(-127, min(127, q));
            p |= ((unsigned int)(q & 0xff)) << (b * 8);
        }
        dst[e / 4] = p;
    }
}

// ---------------- xp GEMM via bf16 mma.sync + cp.async double buffer ---------
__device__ __forceinline__ void ldsm4(unsigned int* r, const void* p) {
    unsigned int sa = (unsigned int)__cvta_generic_to_shared(p);
    asm volatile("ldmatrix.sync.aligned.m8n8.x4.shared.b16 {%0,%1,%2,%3}, [%4];"
                 : "=r"(r[0]), "=r"(r[1]), "=r"(r[2]), "=r"(r[3]) : "r"(sa));
}
__device__ __forceinline__ void mma16816(float* c, const unsigned int* a,
                                         unsigned int b0, unsigned int b1) {
    asm volatile("mma.sync.aligned.m16n8k16.row.col.f32.bf16.bf16.f32 "
                 "{%0,%1,%2,%3}, {%4,%5,%6,%7}, {%8,%9}, {%0,%1,%2,%3};"
                 : "+f"(c[0]), "+f"(c[1]), "+f"(c[2]), "+f"(c[3])
                 : "r"(a[0]), "r"(a[1]), "r"(a[2]), "r"(a[3]), "r"(b0), "r"(b1));
}
__device__ __forceinline__ void cpa16(void* smem, const void* gmem) {
    unsigned int sa = (unsigned int)__cvta_generic_to_shared(smem);
    asm volatile("cp.async.cg.shared.global [%0], [%1], 16;" :: "r"(sa), "l"(gmem));
}

__global__ __launch_bounds__(256, 2)
void xp_gemm_mma(const float* __restrict__ bih1, const float* __restrict__ bih2) {
    __shared__ __nv_bfloat16 As[2][128][40];
    __shared__ __nv_bfloat16 Bs[2][128][40];

    const int gru = blockIdx.z;
    const int bm  = blockIdx.y * 128;
    const int bn  = blockIdx.x * 128;
    const __nv_bfloat16* __restrict__ Ag = &g_xb[gru][0][0];
    const __nv_bfloat16* __restrict__ Bg = &g_wb[gru][0][0];
    const float* __restrict__ bias = gru ? bih2 : bih1;

    const int tid  = threadIdx.x;
    const int warp = tid >> 5;
    const int lane = tid & 31;
    const int wm   = warp & 3;
    const int wn   = warp >> 2;

    float acc[2][8][4];
#pragma unroll
    for (int i = 0; i < 2; i++)
#pragma unroll
        for (int j = 0; j < 8; j++)
#pragma unroll
            for (int k = 0; k < 4; k++) acc[i][j][k] = 0.f;

    auto load_slab = [&](int buf, int k0) {
#pragma unroll
        for (int v = 0; v < 2; v++) {
            const int e  = tid + v * 256;
            const int r  = e >> 2;
            const int cc = (e & 3) * 8;
            cpa16(&As[buf][r][cc], Ag + (size_t)(bm + r) * DD + k0 + cc);
            cpa16(&Bs[buf][r][cc], Bg + (size_t)(bn + r) * DD + k0 + cc);
        }
        asm volatile("cp.async.commit_group;");
    };

    load_slab(0, 0);

    int buf = 0;
    for (int k0 = 0; k0 < DD; k0 += 32, buf ^= 1) {
        asm volatile("cp.async.wait_group 0;");
        __syncthreads();
        if (k0 + 32 < DD) load_slab(buf ^ 1, k0 + 32);

#pragma unroll
        for (int kk = 0; kk < 32; kk += 16) {
            unsigned int a[2][4], b[4][4];
            const int arow = (lane & 15);
            const int acol = kk + 8 * (lane >> 4);
#pragma unroll
            for (int mf = 0; mf < 2; mf++)
                ldsm4(a[mf], &As[buf][wm * 32 + mf * 16 + arow][acol]);
#pragma unroll
            for (int nb = 0; nb < 4; nb++)
                ldsm4(b[nb], &Bs[buf][wn * 64 + nb * 16 + arow][acol]);
#pragma unroll
            for (int mf = 0; mf < 2; mf++)
#pragma unroll
                for (int nb = 0; nb < 4; nb++) {
                    mma16816(acc[mf][nb * 2 + 0], a[mf], b[nb][0], b[nb][2]);
                    mma16816(acc[mf][nb * 2 + 1], a[mf], b[nb][1], b[nb][3]);
                }
        }
        __syncthreads();
    }

    float* __restrict__ C = &g_xp[gru][0][0];
#pragma unroll
    for (int nf = 0; nf < 8; nf++) {
        const int gn = bn + wn * 64 + nf * 8 + (lane & 3) * 2;
        const float b0 = __ldg(bias + gn);
        const float b1 = __ldg(bias + gn + 1);
#pragma unroll
        for (int mf = 0; mf < 2; mf++) {
            const int gm = bm + wm * 32 + mf * 16 + (lane >> 2);
            C[(size_t)gm * G3H + gn]           = acc[mf][nf][0] + b0;
            C[(size_t)gm * G3H + gn + 1]       = acc[mf][nf][1] + b1;
            C[(size_t)(gm + 8) * G3H + gn]     = acc[mf][nf][2] + b0;
            C[(size_t)(gm + 8) * G3H + gn + 1] = acc[mf][nf][3] + b1;
        }
    }
}

// ---------------- persistent GRU scan (R6/R15 form — proven best) ------------
__global__ __launch_bounds__(THREADS, 1)
void gru_scan(const float* __restrict__ bhh1, const float* __restrict__ bhh2) {
    __shared__ uint4 s_r[NW * 128];      // r-gate rows, int8-packed: 56 KB
    __shared__ uint4 s_h[128];           // this GRU's int8 h: 2 KB

    const int tid  = threadIdx.x;
    const int wid  = tid >> 5;
    const int lane = tid & 31;
    const int grp  = (blockIdx.x < GB) ? 0 : 1;          // barrier group == gru
    const int blk  = blockIdx.x - grp * GB;
    const int ol   = blk * NW + wid;                     // local output id
    const bool active = (ol < HH);
    const int i    = active ? ol : 0;
    const int gru  = grp;

    uint4 zr[4], nr[4];
    float fr = 0.f, fz = 0.f, fn = 0.f, br = 0.f, bz = 0.f, bnn = 0.f;
    {
        const uint4* r_row = (const uint4*)&g_wq[gru][i][0];
        const uint4* z_row = (const uint4*)&g_wq[gru][i + HH][0];
        const uint4* n_row = (const uint4*)&g_wq[gru][i + 2 * HH][0];
#pragma unroll
        for (int c = 0; c < 4; c++) {
            s_r[wid * 128 + c * 32 + lane] = r_row[c * 32 + lane];
            zr[c] = z_row[c * 32 + lane];
            nr[c] = n_row[c * 32 + lane];
        }
        fr  = g_wdq[gru][i];
        fz  = g_wdq[gru][i + HH];
        fn  = g_wdq[gru][i + 2 * HH];
        const float* __restrict__ bh = gru ? bhh2 : bhh1;
        br  = bh[i];
        bz  = bh[i + HH];
        bnn = bh[i + 2 * HH];
    }
    float h_own = 0.0f;
    const float* __restrict__ xpg = &g_xp[gru][0][0];

    float xr = 0.f, xz = 0.f, xn = 0.f;
    if (active && lane == 0) {
        xr = __ldg(xpg + i);
        xz = __ldg(xpg + i + HH);
        xn = __ldg(xpg + i + 2 * HH);
    }

    for (int t = 0; t < TT; t++) {
        float pxr = 0.f, pxz = 0.f, pxn = 0.f;
        if (active && lane == 0 && t + 1 < TT) {
            const float* __restrict__ xp = xpg + (size_t)(t + 1) * G3H;
            pxr = __ldg(xp + i);
            pxz = __ldg(xp + i + HH);
            pxn = __ldg(xp + i + 2 * HH);
        }

        if (tid < 128)
            s_h[tid] = __ldcg((const uint4*)g_hq[t & 1][gru] + tid);
        __syncthreads();

        if (active) {
            int accr = 0, accz = 0, accn = 0;
            const uint4* sr = &s_r[wid * 128];
#pragma unroll
            for (int c = 0; c < 4; c++) {
                uint4 h4 = s_h[c * 32 + lane];
                uint4 r4 = sr[c * 32 + lane];
                accr = __dp4a((int)r4.x, (int)h4.x, accr);
                accr = __dp4a((int)r4.y, (int)h4.y, accr);
                accr = __dp4a((int)r4.z, (int)h4.z, accr);
                accr = __dp4a((int)r4.w, (int)h4.w, accr);
                accz = __dp4a((int)zr[c].x, (int)h4.x, accz);
                accz = __dp4a((int)zr[c].y, (int)h4.y, accz);
                accz = __dp4a((int)zr[c].z, (int)h4.z, accz);
                accz = __dp4a((int)zr[c].w, (int)h4.w, accz);
                accn = __dp4a((int)nr[c].x, (int)h4.x, accn);
                accn = __dp4a((int)nr[c].y, (int)h4.y, accn);
                accn = __dp4a((int)nr[c].z, (int)h4.z, accn);
                accn = __dp4a((int)nr[c].w, (int)h4.w, accn);
            }
            accr = __reduce_add_sync(0xffffffffu, accr);
            accz = __reduce_add_sync(0xffffffffu, accz);
            accn = __reduce_add_sync(0xffffffffu, accn);
            if (lane == 0) {
                const float hr = (float)accr * fr + br;
                const float hz = (float)accz * fz + bz;
                const float hn = (float)accn * fn + bnn;
                const float r = __fdividef(1.f, 1.f + __expf(-(xr + hr)));
                const float z = __fdividef(1.f, 1.f + __expf(-(xz + hz)));
                float n;
                asm("tanh.approx.f32 %0, %1;" : "=f"(n) : "f"(xn + r * hn));
                h_own = (1.f - z) * n + z * h_own;
                int q = __float2int_rn(h_own * 127.f);
                q = max(-127, min(127, q));
                g_hq[(t + 1) & 1][gru][i] = (char)q;
            }
        }

        // ---- group barrier: RED release arrival + acquire-load poll ----
        __syncthreads();
        if (tid == 0) {
            asm volatile("red.release.gpu.global.add.u32 [%0], %1;"
                         :: "l"(&g_bar2[grp][0]), "r"(1u) : "memory");
            const unsigned int target = (unsigned int)GB * (unsigned int)(t + 1);
            unsigned int v;
            do {
                asm volatile("ld.acquire.gpu.global.u32 %0, [%1];"
                             : "=r"(v) : "l"(&g_bar2[grp][0]) : "memory");
            } while (v < target);
        }
        __syncthreads();

        xr = pxr; xz = pxz; xn = pxn;
    }

    if (active && lane == 0) g_h32[gru * HH + i] = h_own;
}

// ---------------- head: fc1 (relu) -------------------------------------------
__global__ void head_fc1(const float* __restrict__ w, const float* __restrict__ b) {
    __shared__ float red[256];
    const int row = blockIdx.x, tid = threadIdx.x;
    const float* __restrict__ wr = w + (long long)row * (2 * HH);
    float s = 0.f;
    for (int j = tid; j < 2 * HH; j += 256) s += wr[j] * g_h32[j];
    red[tid] = s; __syncthreads();
    for (int o = 128; o; o >>= 1) { if (tid < o) red[tid] += red[tid + o]; __syncthreads(); }
    if (tid == 0) { const float v = red[0] + b[row]; g_fc1[row] = v > 0.f ? v : 0.f; }
}

// ---------------- head: fc2 + log_softmax ------------------------------------
__global__ void head_fc2(const float* __restrict__ w, const float* __restrict__ b,
                         float* __restrict__ out) {
    __shared__ float logits[3];
    const int tid = threadIdx.x;
    const int wr = tid >> 5, lane = tid & 31;
    float s = 0.f;
    for (int j = lane; j < 256; j += 32) s += w[wr * 256 + j] * g_fc1[j];
#pragma unroll
    for (int off = 16; off; off >>= 1) s += __shfl_down_sync(0xffffffffu, s, off);
    if (lane == 0) logits[wr] = s + b[wr];
    __syncthreads();
    if (tid == 0) {
        const float m = fmaxf(logits[0], fmaxf(logits[1], logits[2]));
        const float l = logf(expf(logits[0] - m) + expf(logits[1] - m) + expf(logits[2] - m));
        out[0] = logits[0] - m - l;
        out[1] = logits[1] - m - l;
        out[2] = logits[2] - m - l;
    }
}

// ---------------- launcher ----------------------------------------------------
extern "C" void kernel_launch(void* const* d_in, const int* in_sizes, int n_in,
                              void* d_out, int out_size) {
    const float* x1    = (const float*)d_in[0];
    const float* x2    = (const float*)d_in[1];
    const float* W_ih1 = (const float*)d_in[2];
    const float* W_hh1 = (const float*)d_in[3];
    const float* b_ih1 = (const float*)d_in[4];
    const float* b_hh1 = (const float*)d_in[5];
    const float* W_ih2 = (const float*)d_in[6];
    const float* W_hh2 = (const float*)d_in[7];
    const float* b_ih2 = (const float*)d_in[8];
    const float* b_hh2 = (const float*)d_in[9];
    const float* fc1_w = (const float*)d_in[10];
    const float* fc1_b = (const float*)d_in[11];
    const float* fc2_w = (const float*)d_in[12];
    const float* fc2_b = (const float*)d_in[13];
    float* out = (float*)d_out;

    conv_bf16<<<1024, 256>>>(x1, x2, W_ih1, W_ih2);
    quant_kernel<<<2 * G3H, 256>>>(W_hh1, W_hh2);
    xp_gemm_mma<<<dim3(G3H / 128, TT / 128, 2), 256>>>(b_ih1, b_ih2);
    gru_scan<<<NB, THREADS>>>(b_hh1, b_hh2);
    head_fc1<<<256, 256>>>(fc1_w, fc1_b);
    head_fc2<<<1, 96>>>(fc2_w, fc2_b, out);
}